// round 9
// baseline (speedup 1.0000x reference)
#include <cuda_runtime.h>
#include <cuda_bf16.h>
#include <math.h>

// Shapes (fixed by the problem)
#define BB   16       // batch
#define LL   128      // seq len
#define VV   32000    // vocab
#define EE   512      // emb dim
#define HH   1024     // hidden
#define DD   512      // latent dim
#define STEPS 127     // L-1 recurrence steps
#define MM   (STEPS*BB)   // 2032 rows, time-major (m = s*16 + b)

#define TBM 128       // GEMM tile M
#define TBN 128       // GEMM tile N
#define TBK 16        // GEMM tile K

// -------- scratch (static device globals; no allocation) --------
__device__ float g_Z[MM * 4 * HH];     // pre-activation input gates (33.3 MB)
__device__ float g_H[MM * HH];         // all hidden states (8.3 MB)
__device__ float g_C[BB * HH];         // cell state
__device__ float g_Lp[BB * 4 * HH];    // latent @ W_ih[:,E:]^T + bias

// =====================================================================
// zero out[:, 0, :]
// =====================================================================
__global__ void k_zero(float* __restrict__ out) {
    int i = blockIdx.x * 256 + threadIdx.x;     // 16 * 8000 float4
    if (i < BB * (VV / 4)) {
        int b  = i / (VV / 4);
        int v4 = i % (VV / 4);
        float4 z = {0.f, 0.f, 0.f, 0.f};
        ((float4*)(out + (size_t)b * LL * VV))[v4] = z;
    }
}

// =====================================================================
// Lp[b][j] = b_ih[j] + b_hh[j] + latent[b] . W_ih[j, 512:1024]
// =====================================================================
__global__ void __launch_bounds__(256) k_lat(
    const float* __restrict__ latent, const float* __restrict__ W_ih,
    const float* __restrict__ b_ih,   const float* __restrict__ b_hh) {
    int g = blockIdx.x * 256 + threadIdx.x;   // 65536
    int j = g >> 4;
    int b = g & 15;
    const float4* wl = (const float4*)(W_ih + (size_t)j * (EE + DD) + EE);
    const float4* lv = (const float4*)(latent + b * DD);
    float acc = 0.f;
#pragma unroll 8
    for (int k = 0; k < DD / 4; k++) {
        float4 w = wl[k], x = lv[k];
        acc += w.x * x.x + w.y * x.y + w.z * x.z + w.w * x.w;
    }
    g_Lp[b * 4 * HH + j] = acc + b_ih[j] + b_hh[j];
}

// =====================================================================
// Z = gather(emb, tok) @ W_ih[:, :512]^T + Lp
//   M=2032, N=4096, K=512.  A row m -> emb[target[(m%16)*128 + (m/16)]]
// =====================================================================
__global__ void __launch_bounds__(256) k_z(
    const float* __restrict__ emb, const float* __restrict__ W_ih,
    const int* __restrict__ target) {
    const int M = MM, K = EE, ldb = EE + DD;
    __shared__ float As[2][TBK][TBM + 4];
    __shared__ float Bs[2][TBK][TBN + 4];
    int tid = threadIdx.x;
    int m0 = blockIdx.y * TBM;
    int n0 = blockIdx.x * TBN;

    int lr = tid >> 2;            // 0..63
    int lk = (tid & 3) * 4;       // 0,4,8,12

    int r1 = m0 + lr, r2 = m0 + lr + 64;
    bool v1 = (r1 < M), v2 = (r2 < M);
    const float* arow1 = emb + (size_t)(v1 ? target[(r1 & 15) * LL + (r1 >> 4)] : 0) * EE;
    const float* arow2 = emb + (size_t)(v2 ? target[(r2 & 15) * LL + (r2 >> 4)] : 0) * EE;
    const float* brow1 = W_ih + (size_t)(n0 + lr) * ldb;
    const float* brow2 = W_ih + (size_t)(n0 + lr + 64) * ldb;

    float acc[8][8];
#pragma unroll
    for (int i = 0; i < 8; i++)
#pragma unroll
        for (int j = 0; j < 8; j++) acc[i][j] = 0.f;

    int tx = tid & 15, ty = tid >> 4;
    const float4 zero4 = {0.f, 0.f, 0.f, 0.f};

    float4 pa0, pa1, pb0, pb1;
    {
        int gk = lk;
        pa0 = v1 ? *(const float4*)(arow1 + gk) : zero4;
        pa1 = v2 ? *(const float4*)(arow2 + gk) : zero4;
        pb0 = *(const float4*)(brow1 + gk);
        pb1 = *(const float4*)(brow2 + gk);
        As[0][lk + 0][lr] = pa0.x; As[0][lk + 1][lr] = pa0.y; As[0][lk + 2][lr] = pa0.z; As[0][lk + 3][lr] = pa0.w;
        As[0][lk + 0][lr + 64] = pa1.x; As[0][lk + 1][lr + 64] = pa1.y; As[0][lk + 2][lr + 64] = pa1.z; As[0][lk + 3][lr + 64] = pa1.w;
        Bs[0][lk + 0][lr] = pb0.x; Bs[0][lk + 1][lr] = pb0.y; Bs[0][lk + 2][lr] = pb0.z; Bs[0][lk + 3][lr] = pb0.w;
        Bs[0][lk + 0][lr + 64] = pb1.x; Bs[0][lk + 1][lr + 64] = pb1.y; Bs[0][lk + 2][lr + 64] = pb1.z; Bs[0][lk + 3][lr + 64] = pb1.w;
    }
    __syncthreads();

    const int NT = K / TBK;   // 32
    int cur = 0;
    for (int kt = 0; kt < NT; kt++) {
        if (kt + 1 < NT) {
            int gk = (kt + 1) * TBK + lk;
            pa0 = v1 ? *(const float4*)(arow1 + gk) : zero4;
            pa1 = v2 ? *(const float4*)(arow2 + gk) : zero4;
            pb0 = *(const float4*)(brow1 + gk);
            pb1 = *(const float4*)(brow2 + gk);
        }
#pragma unroll
        for (int k = 0; k < TBK; k++) {
            float4 a0 = *(const float4*)&As[cur][k][ty * 4];
            float4 a1 = *(const float4*)&As[cur][k][ty * 4 + 64];
            float4 b0 = *(const float4*)&Bs[cur][k][tx * 4];
            float4 b1 = *(const float4*)&Bs[cur][k][tx * 4 + 64];
            float a[8] = {a0.x, a0.y, a0.z, a0.w, a1.x, a1.y, a1.z, a1.w};
            float b[8] = {b0.x, b0.y, b0.z, b0.w, b1.x, b1.y, b1.z, b1.w};
#pragma unroll
            for (int i = 0; i < 8; i++)
#pragma unroll
                for (int j = 0; j < 8; j++) acc[i][j] += a[i] * b[j];
        }
        if (kt + 1 < NT) {
            int nx = cur ^ 1;
            As[nx][lk + 0][lr] = pa0.x; As[nx][lk + 1][lr] = pa0.y; As[nx][lk + 2][lr] = pa0.z; As[nx][lk + 3][lr] = pa0.w;
            As[nx][lk + 0][lr + 64] = pa1.x; As[nx][lk + 1][lr + 64] = pa1.y; As[nx][lk + 2][lr + 64] = pa1.z; As[nx][lk + 3][lr + 64] = pa1.w;
            Bs[nx][lk + 0][lr] = pb0.x; Bs[nx][lk + 1][lr] = pb0.y; Bs[nx][lk + 2][lr] = pb0.z; Bs[nx][lk + 3][lr] = pb0.w;
            Bs[nx][lk + 0][lr + 64] = pb1.x; Bs[nx][lk + 1][lr + 64] = pb1.y; Bs[nx][lk + 2][lr + 64] = pb1.z; Bs[nx][lk + 3][lr + 64] = pb1.w;
            __syncthreads();
            cur = nx;
        }
    }

#pragma unroll
    for (int i = 0; i < 8; i++) {
        int m = m0 + ty * 4 + (i & 3) + ((i >= 4) ? 64 : 0);
        if (m < M) {
            int b = m & 15;
            const float4 l0 = *(const float4*)(g_Lp + b * 4 * HH + n0 + tx * 4);
            const float4 l1 = *(const float4*)(g_Lp + b * 4 * HH + n0 + tx * 4 + 64);
            float4 v0 = {acc[i][0] + l0.x, acc[i][1] + l0.y, acc[i][2] + l0.z, acc[i][3] + l0.w};
            float4 w0 = {acc[i][4] + l1.x, acc[i][5] + l1.y, acc[i][6] + l1.z, acc[i][7] + l1.w};
            float* zrow = g_Z + (size_t)m * 4 * HH + n0 + tx * 4;
            *(float4*)zrow = v0;
            *(float4*)(zrow + 64) = w0;
        }
    }
}

// =====================================================================
// One LSTM step: gates = Z[t] + h_{t-1} @ W_hh^T; cell update; h -> g_H[t]
// grid 128 x 256 thr. warp w -> jh = blk*8+w; lane: b = lane>>1, gp = lane&1
// gp=0 computes gates (i,f), gp=1 computes (g,o); shfl_xor(1) exchanges.
// =====================================================================
__device__ __forceinline__ float sigf(float x) { return 1.0f / (1.0f + expf(-x)); }

__global__ void __launch_bounds__(256) k_step(const float* __restrict__ Whh, int t) {
    int warp = threadIdx.x >> 5;
    int lane = threadIdx.x & 31;
    int b  = lane >> 1;
    int gp = lane & 1;
    int jh = blockIdx.x * 8 + warp;

    float acc0 = 0.f, acc1 = 0.f;
    if (t > 0) {
        const float4* w0 = (const float4*)(Whh + ((size_t)(2 * gp)     * HH + jh) * HH);
        const float4* w1 = (const float4*)(Whh + ((size_t)(2 * gp + 1) * HH + jh) * HH);
        const float4* hv = (const float4*)(g_H + ((size_t)(t - 1) * BB + b) * HH);
#pragma unroll 4
        for (int k = 0; k < HH / 4; k++) {
            float4 a = w0[k];
            float4 c = w1[k];
            float4 h = hv[k];
            acc0 += a.x * h.x + a.y * h.y + a.z * h.z + a.w * h.w;
            acc1 += c.x * h.x + c.y * h.y + c.z * h.z + c.w * h.w;
        }
    }
    const float* Zr = g_Z + ((size_t)t * BB + b) * 4 * HH;
    float p0 = acc0 + Zr[(2 * gp)     * HH + jh];
    float p1 = acc1 + Zr[(2 * gp + 1) * HH + jh];
    float q0 = __shfl_xor_sync(0xffffffffu, p0, 1);
    float q1 = __shfl_xor_sync(0xffffffffu, p1, 1);
    float gi, gf, gg, go;
    if (gp == 0) { gi = p0; gf = p1; gg = q0; go = q1; }
    else         { gi = q0; gf = q1; gg = p0; go = p1; }
    float cprev = (t == 0) ? 0.f : g_C[b * HH + jh];
    float cn = sigf(gf) * cprev + sigf(gi) * tanhf(gg);
    float hn = sigf(go) * tanhf(cn);
    if (gp == 0) {
        g_C[b * HH + jh] = cn;
        g_H[((size_t)t * BB + b) * HH + jh] = hn;
    }
}

// =====================================================================
// logits = H_all @ fc_w^T + fc_b -> out[b, t+1, :]
//   M=2032, N=32000, K=1024
// =====================================================================
__global__ void __launch_bounds__(256) k_logits(
    const float* __restrict__ fc_w, const float* __restrict__ fc_b,
    float* __restrict__ out) {
    const int M = MM, K = HH;
    __shared__ float As[2][TBK][TBM + 4];
    __shared__ float Bs[2][TBK][TBN + 4];
    int tid = threadIdx.x;
    int m0 = blockIdx.y * TBM;
    int n0 = blockIdx.x * TBN;

    int lr = tid >> 2;
    int lk = (tid & 3) * 4;

    int r1 = m0 + lr, r2 = m0 + lr + 64;
    bool v1 = (r1 < M), v2 = (r2 < M);
    const float* arow1 = g_H + (size_t)(v1 ? r1 : 0) * K;
    const float* arow2 = g_H + (size_t)(v2 ? r2 : 0) * K;
    const float* brow1 = fc_w + (size_t)(n0 + lr) * K;
    const float* brow2 = fc_w + (size_t)(n0 + lr + 64) * K;

    float acc[8][8];
#pragma unroll
    for (int i = 0; i < 8; i++)
#pragma unroll
        for (int j = 0; j < 8; j++) acc[i][j] = 0.f;

    int tx = tid & 15, ty = tid >> 4;
    const float4 zero4 = {0.f, 0.f, 0.f, 0.f};

    float4 pa0, pa1, pb0, pb1;
    {
        int gk = lk;
        pa0 = v1 ? *(const float4*)(arow1 + gk) : zero4;
        pa1 = v2 ? *(const float4*)(arow2 + gk) : zero4;
        pb0 = *(const float4*)(brow1 + gk);
        pb1 = *(const float4*)(brow2 + gk);
        As[0][lk + 0][lr] = pa0.x; As[0][lk + 1][lr] = pa0.y; As[0][lk + 2][lr] = pa0.z; As[0][lk + 3][lr] = pa0.w;
        As[0][lk + 0][lr + 64] = pa1.x; As[0][lk + 1][lr + 64] = pa1.y; As[0][lk + 2][lr + 64] = pa1.z; As[0][lk + 3][lr + 64] = pa1.w;
        Bs[0][lk + 0][lr] = pb0.x; Bs[0][lk + 1][lr] = pb0.y; Bs[0][lk + 2][lr] = pb0.z; Bs[0][lk + 3][lr] = pb0.w;
        Bs[0][lk + 0][lr + 64] = pb1.x; Bs[0][lk + 1][lr + 64] = pb1.y; Bs[0][lk + 2][lr + 64] = pb1.z; Bs[0][lk + 3][lr + 64] = pb1.w;
    }
    __syncthreads();

    const int NT = K / TBK;   // 64
    int cur = 0;
    for (int kt = 0; kt < NT; kt++) {
        if (kt + 1 < NT) {
            int gk = (kt + 1) * TBK + lk;
            pa0 = v1 ? *(const float4*)(arow1 + gk) : zero4;
            pa1 = v2 ? *(const float4*)(arow2 + gk) : zero4;
            pb0 = *(const float4*)(brow1 + gk);
            pb1 = *(const float4*)(brow2 + gk);
        }
#pragma unroll
        for (int k = 0; k < TBK; k++) {
            float4 a0 = *(const float4*)&As[cur][k][ty * 4];
            float4 a1 = *(const float4*)&As[cur][k][ty * 4 + 64];
            float4 b0 = *(const float4*)&Bs[cur][k][tx * 4];
            float4 b1 = *(const float4*)&Bs[cur][k][tx * 4 + 64];
            float a[8] = {a0.x, a0.y, a0.z, a0.w, a1.x, a1.y, a1.z, a1.w};
            float b[8] = {b0.x, b0.y, b0.z, b0.w, b1.x, b1.y, b1.z, b1.w};
#pragma unroll
            for (int i = 0; i < 8; i++)
#pragma unroll
                for (int j = 0; j < 8; j++) acc[i][j] += a[i] * b[j];
        }
        if (kt + 1 < NT) {
            int nx = cur ^ 1;
            As[nx][lk + 0][lr] = pa0.x; As[nx][lk + 1][lr] = pa0.y; As[nx][lk + 2][lr] = pa0.z; As[nx][lk + 3][lr] = pa0.w;
            As[nx][lk + 0][lr + 64] = pa1.x; As[nx][lk + 1][lr + 64] = pa1.y; As[nx][lk + 2][lr + 64] = pa1.z; As[nx][lk + 3][lr + 64] = pa1.w;
            Bs[nx][lk + 0][lr] = pb0.x; Bs[nx][lk + 1][lr] = pb0.y; Bs[nx][lk + 2][lr] = pb0.z; Bs[nx][lk + 3][lr] = pb0.w;
            Bs[nx][lk + 0][lr + 64] = pb1.x; Bs[nx][lk + 1][lr + 64] = pb1.y; Bs[nx][lk + 2][lr + 64] = pb1.z; Bs[nx][lk + 3][lr + 64] = pb1.w;
            __syncthreads();
            cur = nx;
        }
    }

    float4 bias0 = *(const float4*)(fc_b + n0 + tx * 4);
    float4 bias1 = *(const float4*)(fc_b + n0 + tx * 4 + 64);
#pragma unroll
    for (int i = 0; i < 8; i++) {
        int m = m0 + ty * 4 + (i & 3) + ((i >= 4) ? 64 : 0);
        if (m < M) {
            int t = m >> 4, b = m & 15;
            float* orow = out + ((size_t)b * LL + (t + 1)) * VV + n0 + tx * 4;
            float4 v0 = {acc[i][0] + bias0.x, acc[i][1] + bias0.y, acc[i][2] + bias0.z, acc[i][3] + bias0.w};
            float4 w0 = {acc[i][4] + bias1.x, acc[i][5] + bias1.y, acc[i][6] + bias1.z, acc[i][7] + bias1.w};
            *(float4*)orow = v0;
            *(float4*)(orow + 64) = w0;
        }
    }
}

// =====================================================================
// Launch
// =====================================================================
extern "C" void kernel_launch(void* const* d_in, const int* in_sizes, int n_in,
                              void* d_out, int out_size) {
    const float* latent = (const float*)d_in[0];   // (16, 512)
    const float* emb    = (const float*)d_in[1];   // (32000, 512)
    const float* W_ih   = (const float*)d_in[2];   // (4096, 1024)
    const float* W_hh   = (const float*)d_in[3];   // (4096, 1024)
    const float* b_ih   = (const float*)d_in[4];   // (4096,)
    const float* b_hh   = (const float*)d_in[5];   // (4096,)
    const float* fc_w   = (const float*)d_in[6];   // (32000, 1024)
    const float* fc_b   = (const float*)d_in[7];   // (32000,)
    const int*   target = (const int*)d_in[8];     // (16, 128)
    // d_in[9] = tf_mask: all True (teacher forcing) -> recurrence independent of logits
    float* out = (float*)d_out;                    // (16, 128, 32000)
    (void)in_sizes; (void)n_in; (void)out_size;

    k_zero<<<(BB * (VV / 4) + 255) / 256, 256>>>(out);
    k_lat<<<(BB * 4 * HH) / 256, 256>>>(latent, W_ih, b_ih, b_hh);

    {
        dim3 grid(4 * HH / TBN, (MM + TBM - 1) / TBM);   // (32, 16)
        k_z<<<grid, 256>>>(emb, W_ih, target);
    }

    for (int t = 0; t < STEPS; t++) {
        k_step<<<HH / 8, 256>>>(W_hh, t);
    }

    {
        dim3 grid(VV / TBN, (MM + TBM - 1) / TBM);       // (250, 16)
        k_logits<<<grid, 256>>>(fc_w, fc_b, out);
    }
}

// round 11
// speedup vs baseline: 1.3177x; 1.3177x over previous
#include <cuda_runtime.h>
#include <cuda_bf16.h>
#include <math.h>
#include <stdint.h>

// Shapes (fixed by the problem)
#define BB   16
#define LL   128
#define VV   32000
#define EE   512
#define HH   1024
#define DD   512
#define STEPS 127
#define MM   (STEPS*BB)     // 2032, time-major m = t*16 + b
#define MPAD 2048

#define TBM 128
#define TBN 128
#define TBK 16

// -------- scratch (static device globals; no allocation) --------
__device__ float g_Z[MM * 4 * HH];
__device__ float g_H[MM * HH];
__device__ float g_C[BB * HH];
__device__ float g_Lp[BB * 4 * HH];
__device__ __nv_bfloat16 g_Hhi[(size_t)MPAD * HH];
__device__ __nv_bfloat16 g_Hlo[(size_t)MPAD * HH];
__device__ __nv_bfloat16 g_Whi[(size_t)VV * HH];
__device__ __nv_bfloat16 g_Wlo[(size_t)VV * HH];

// ============================ PTX helpers (sm_80-era, family-safe) ============
static __device__ __forceinline__ uint32_t s2u(const void* p) {
    uint32_t a;
    asm("{ .reg .u64 t; cvta.to.shared.u64 t, %1; cvt.u32.u64 %0, t; }"
        : "=r"(a) : "l"(p));
    return a;
}

__device__ __forceinline__ void mma16816(float* c, uint32_t a0, uint32_t a1,
                                         uint32_t a2, uint32_t a3,
                                         uint32_t b0, uint32_t b1) {
    asm volatile(
        "mma.sync.aligned.m16n8k16.row.col.f32.bf16.bf16.f32 "
        "{%0,%1,%2,%3}, {%4,%5,%6,%7}, {%8,%9}, {%0,%1,%2,%3};"
        : "+f"(c[0]), "+f"(c[1]), "+f"(c[2]), "+f"(c[3])
        : "r"(a0), "r"(a1), "r"(a2), "r"(a3), "r"(b0), "r"(b1));
}

__device__ __forceinline__ void ldm_x4(uint32_t* r, uint32_t addr) {
    asm volatile("ldmatrix.sync.aligned.m8n8.x4.shared.b16 {%0,%1,%2,%3}, [%4];"
        : "=r"(r[0]), "=r"(r[1]), "=r"(r[2]), "=r"(r[3]) : "r"(addr));
}

#define CP16(dst, src) \
    asm volatile("cp.async.ca.shared.global [%0], [%1], 16;" :: "r"(dst), "l"(src))
#define CP_COMMIT()  asm volatile("cp.async.commit_group;" ::: "memory")
#define CP_WAIT1()   asm volatile("cp.async.wait_group 1;" ::: "memory")
#define CP_WAIT0()   asm volatile("cp.async.wait_group 0;" ::: "memory")

// =====================================================================
// zero out[:, 0, :]
// =====================================================================
__global__ void k_zero(float* __restrict__ out) {
    int i = blockIdx.x * 256 + threadIdx.x;
    if (i < BB * (VV / 4)) {
        int b  = i / (VV / 4);
        int v4 = i % (VV / 4);
        float4 z = {0.f, 0.f, 0.f, 0.f};
        ((float4*)(out + (size_t)b * LL * VV))[v4] = z;
    }
}

// =====================================================================
// Lp[b][j] = b_ih[j] + b_hh[j] + latent[b] . W_ih[j, 512:1024]
// =====================================================================
__global__ void __launch_bounds__(256) k_lat(
    const float* __restrict__ latent, const float* __restrict__ W_ih,
    const float* __restrict__ b_ih,   const float* __restrict__ b_hh) {
    int g = blockIdx.x * 256 + threadIdx.x;
    int j = g >> 4;
    int b = g & 15;
    const float4* wl = (const float4*)(W_ih + (size_t)j * (EE + DD) + EE);
    const float4* lv = (const float4*)(latent + b * DD);
    float acc = 0.f;
#pragma unroll 8
    for (int k = 0; k < DD / 4; k++) {
        float4 w = wl[k], x = lv[k];
        acc += w.x * x.x + w.y * x.y + w.z * x.z + w.w * x.w;
    }
    g_Lp[b * 4 * HH + j] = acc + b_ih[j] + b_hh[j];
}

// =====================================================================
// split fc_w into bf16 hi/lo
// =====================================================================
__global__ void __launch_bounds__(256) k_split_w(const float* __restrict__ fc_w) {
    size_t i = (size_t)blockIdx.x * 256 + threadIdx.x;
    if (i < (size_t)VV * HH / 4) {
        float4 v = ((const float4*)fc_w)[i];
        __nv_bfloat16 h0 = __float2bfloat16(v.x);
        __nv_bfloat16 h1 = __float2bfloat16(v.y);
        __nv_bfloat16 h2 = __float2bfloat16(v.z);
        __nv_bfloat16 h3 = __float2bfloat16(v.w);
        __nv_bfloat16 l0 = __float2bfloat16(v.x - __bfloat162float(h0));
        __nv_bfloat16 l1 = __float2bfloat16(v.y - __bfloat162float(h1));
        __nv_bfloat16 l2 = __float2bfloat16(v.z - __bfloat162float(h2));
        __nv_bfloat16 l3 = __float2bfloat16(v.w - __bfloat162float(h3));
        uint2 hi, lo;
        hi.x = ((uint32_t)__bfloat16_as_ushort(h1) << 16) | __bfloat16_as_ushort(h0);
        hi.y = ((uint32_t)__bfloat16_as_ushort(h3) << 16) | __bfloat16_as_ushort(h2);
        lo.x = ((uint32_t)__bfloat16_as_ushort(l1) << 16) | __bfloat16_as_ushort(l0);
        lo.y = ((uint32_t)__bfloat16_as_ushort(l3) << 16) | __bfloat16_as_ushort(l2);
        ((uint2*)g_Whi)[i] = hi;
        ((uint2*)g_Wlo)[i] = lo;
    }
}

// zero pad rows 2032..2047 of the H splits
__global__ void k_padH() {
    int i = blockIdx.x * 256 + threadIdx.x;
    if (i < (MPAD - MM) * HH) {
        g_Hhi[(size_t)MM * HH + i] = __float2bfloat16(0.f);
        g_Hlo[(size_t)MM * HH + i] = __float2bfloat16(0.f);
    }
}

// =====================================================================
// Z = gather(emb, tok) @ W_ih[:, :512]^T + Lp   (fp32 SGEMM)
// =====================================================================
__global__ void __launch_bounds__(256) k_z(
    const float* __restrict__ emb, const float* __restrict__ W_ih,
    const int* __restrict__ target) {
    const int M = MM, K = EE, ldb = EE + DD;
    __shared__ float As[2][TBK][TBM + 4];
    __shared__ float Bs[2][TBK][TBN + 4];
    int tid = threadIdx.x;
    int m0 = blockIdx.y * TBM;
    int n0 = blockIdx.x * TBN;

    int lr = tid >> 2;
    int lk = (tid & 3) * 4;

    int r1 = m0 + lr, r2 = m0 + lr + 64;
    bool v1 = (r1 < M), v2 = (r2 < M);
    const float* arow1 = emb + (size_t)(v1 ? target[(r1 & 15) * LL + (r1 >> 4)] : 0) * EE;
    const float* arow2 = emb + (size_t)(v2 ? target[(r2 & 15) * LL + (r2 >> 4)] : 0) * EE;
    const float* brow1 = W_ih + (size_t)(n0 + lr) * ldb;
    const float* brow2 = W_ih + (size_t)(n0 + lr + 64) * ldb;

    float acc[8][8];
#pragma unroll
    for (int i = 0; i < 8; i++)
#pragma unroll
        for (int j = 0; j < 8; j++) acc[i][j] = 0.f;

    int tx = tid & 15, ty = tid >> 4;
    const float4 zero4 = {0.f, 0.f, 0.f, 0.f};

    float4 pa0, pa1, pb0, pb1;
    {
        int gk = lk;
        pa0 = v1 ? *(const float4*)(arow1 + gk) : zero4;
        pa1 = v2 ? *(const float4*)(arow2 + gk) : zero4;
        pb0 = *(const float4*)(brow1 + gk);
        pb1 = *(const float4*)(brow2 + gk);
        As[0][lk + 0][lr] = pa0.x; As[0][lk + 1][lr] = pa0.y; As[0][lk + 2][lr] = pa0.z; As[0][lk + 3][lr] = pa0.w;
        As[0][lk + 0][lr + 64] = pa1.x; As[0][lk + 1][lr + 64] = pa1.y; As[0][lk + 2][lr + 64] = pa1.z; As[0][lk + 3][lr + 64] = pa1.w;
        Bs[0][lk + 0][lr] = pb0.x; Bs[0][lk + 1][lr] = pb0.y; Bs[0][lk + 2][lr] = pb0.z; Bs[0][lk + 3][lr] = pb0.w;
        Bs[0][lk + 0][lr + 64] = pb1.x; Bs[0][lk + 1][lr + 64] = pb1.y; Bs[0][lk + 2][lr + 64] = pb1.z; Bs[0][lk + 3][lr + 64] = pb1.w;
    }
    __syncthreads();

    const int NT = K / TBK;
    int cur = 0;
    for (int kt = 0; kt < NT; kt++) {
        if (kt + 1 < NT) {
            int gk = (kt + 1) * TBK + lk;
            pa0 = v1 ? *(const float4*)(arow1 + gk) : zero4;
            pa1 = v2 ? *(const float4*)(arow2 + gk) : zero4;
            pb0 = *(const float4*)(brow1 + gk);
            pb1 = *(const float4*)(brow2 + gk);
        }
#pragma unroll
        for (int k = 0; k < TBK; k++) {
            float4 a0 = *(const float4*)&As[cur][k][ty * 4];
            float4 a1 = *(const float4*)&As[cur][k][ty * 4 + 64];
            float4 b0 = *(const float4*)&Bs[cur][k][tx * 4];
            float4 b1 = *(const float4*)&Bs[cur][k][tx * 4 + 64];
            float a[8] = {a0.x, a0.y, a0.z, a0.w, a1.x, a1.y, a1.z, a1.w};
            float b[8] = {b0.x, b0.y, b0.z, b0.w, b1.x, b1.y, b1.z, b1.w};
#pragma unroll
            for (int i = 0; i < 8; i++)
#pragma unroll
                for (int j = 0; j < 8; j++) acc[i][j] += a[i] * b[j];
        }
        if (kt + 1 < NT) {
            int nx = cur ^ 1;
            As[nx][lk + 0][lr] = pa0.x; As[nx][lk + 1][lr] = pa0.y; As[nx][lk + 2][lr] = pa0.z; As[nx][lk + 3][lr] = pa0.w;
            As[nx][lk + 0][lr + 64] = pa1.x; As[nx][lk + 1][lr + 64] = pa1.y; As[nx][lk + 2][lr + 64] = pa1.z; As[nx][lk + 3][lr + 64] = pa1.w;
            Bs[nx][lk + 0][lr] = pb0.x; Bs[nx][lk + 1][lr] = pb0.y; Bs[nx][lk + 2][lr] = pb0.z; Bs[nx][lk + 3][lr] = pb0.w;
            Bs[nx][lk + 0][lr + 64] = pb1.x; Bs[nx][lk + 1][lr + 64] = pb1.y; Bs[nx][lk + 2][lr + 64] = pb1.z; Bs[nx][lk + 3][lr + 64] = pb1.w;
            __syncthreads();
            cur = nx;
        }
    }

#pragma unroll
    for (int i = 0; i < 8; i++) {
        int m = m0 + ty * 4 + (i & 3) + ((i >= 4) ? 64 : 0);
        if (m < M) {
            int b = m & 15;
            const float4 l0 = *(const float4*)(g_Lp + b * 4 * HH + n0 + tx * 4);
            const float4 l1 = *(const float4*)(g_Lp + b * 4 * HH + n0 + tx * 4 + 64);
            float4 v0 = {acc[i][0] + l0.x, acc[i][1] + l0.y, acc[i][2] + l0.z, acc[i][3] + l0.w};
            float4 w0 = {acc[i][4] + l1.x, acc[i][5] + l1.y, acc[i][6] + l1.z, acc[i][7] + l1.w};
            float* zrow = g_Z + (size_t)m * 4 * HH + n0 + tx * 4;
            *(float4*)zrow = v0;
            *(float4*)(zrow + 64) = w0;
        }
    }
}

// =====================================================================
// One LSTM step. 256 blocks x 128 thr; warp w -> jh = blk*4+w.
// =====================================================================
__device__ __forceinline__ float sigf(float x) { return 1.0f / (1.0f + expf(-x)); }

__global__ void __launch_bounds__(128) k_step(const float* __restrict__ Whh, int t) {
    int warp = threadIdx.x >> 5;
    int lane = threadIdx.x & 31;
    int b  = lane >> 1;
    int gp = lane & 1;
    int jh = blockIdx.x * 4 + warp;

    float a0 = 0.f, a1 = 0.f, a2 = 0.f, a3 = 0.f;
    if (t > 0) {
        const float4* w0 = (const float4*)(Whh + ((size_t)(2 * gp)     * HH + jh) * HH);
        const float4* w1 = (const float4*)(Whh + ((size_t)(2 * gp + 1) * HH + jh) * HH);
        const float4* hv = (const float4*)(g_H + ((size_t)(t - 1) * BB + b) * HH);
#pragma unroll 4
        for (int k = 0; k < HH / 4; k += 2) {
            float4 x  = w0[k],     y  = w1[k],     h  = hv[k];
            a0 += x.x * h.x + x.y * h.y + x.z * h.z + x.w * h.w;
            a1 += y.x * h.x + y.y * h.y + y.z * h.z + y.w * h.w;
            float4 x2 = w0[k + 1], y2 = w1[k + 1], h2 = hv[k + 1];
            a2 += x2.x * h2.x + x2.y * h2.y + x2.z * h2.z + x2.w * h2.w;
            a3 += y2.x * h2.x + y2.y * h2.y + y2.z * h2.z + y2.w * h2.w;
        }
    }
    const float* Zr = g_Z + ((size_t)t * BB + b) * 4 * HH;
    float p0 = a0 + a2 + Zr[(2 * gp)     * HH + jh];
    float p1 = a1 + a3 + Zr[(2 * gp + 1) * HH + jh];
    float q0 = __shfl_xor_sync(0xffffffffu, p0, 1);
    float q1 = __shfl_xor_sync(0xffffffffu, p1, 1);
    float gi, gf, gg, go;
    if (gp == 0) { gi = p0; gf = p1; gg = q0; go = q1; }
    else         { gi = q0; gf = q1; gg = p0; go = p1; }
    float cprev = (t == 0) ? 0.f : g_C[b * HH + jh];
    float cn = sigf(gf) * cprev + sigf(gi) * tanhf(gg);
    float hn = sigf(go) * tanhf(cn);
    if (gp == 0) {
        g_C[b * HH + jh] = cn;
        size_t ho = ((size_t)t * BB + b) * HH + jh;
        g_H[ho] = hn;
        __nv_bfloat16 hh = __float2bfloat16(hn);
        g_Hhi[ho] = hh;
        g_Hlo[ho] = __float2bfloat16(hn - __bfloat162float(hh));
    }
}

// =====================================================================
// logits via mma.sync bf16 3-product split:
//   D = Ahi*Bhi + Ahi*Blo + Alo*Bhi  (fp32 accum)
// CTA tile 128x128, BK=32, 8 warps (2x4), warp tile 64x32 (4x4 m16n8k16).
// cp.async double-buffered smem; 80B-padded rows (conflict-free ldmatrix).
// grid (16 M-tiles fastest, 250 N-tiles) for L2 reuse of the B strip.
// =====================================================================
#define LROW 80                         // bytes per padded smem row (32 bf16 + pad)
#define TILEB (128 * LROW)              // 10240 B per tile
#define STAGEB (4 * TILEB)              // Ahi, Alo, Bhi, Blo
#define LOG_SMEM (2 * STAGEB)           // 81920 B

__global__ void __launch_bounds__(256) k_logits_mma(
    const float* __restrict__ fc_b, float* __restrict__ out) {
    extern __shared__ char smem[];
    const uint32_t sb = s2u(smem);

    const int tid = threadIdx.x;
    const int wid = tid >> 5, lane = tid & 31;
    const int warp_m = wid >> 2;        // 0..1
    const int warp_n = wid & 3;         // 0..3
    const int m0 = blockIdx.x * 128;
    const int n0 = blockIdx.y * 128;

    const __nv_bfloat16* gsrc[4] = {
        g_Hhi + (size_t)m0 * HH,
        g_Hlo + (size_t)m0 * HH,
        g_Whi + (size_t)n0 * HH,
        g_Wlo + (size_t)n0 * HH
    };

    float acc[4][4][4];
#pragma unroll
    for (int i = 0; i < 4; i++)
#pragma unroll
        for (int j = 0; j < 4; j++)
#pragma unroll
            for (int q = 0; q < 4; q++) acc[i][j][q] = 0.f;

    // ---- async stage loader: 4 tiles x 128 rows x 2 chunks(16B) = 1024 ops / 256 thr
    auto load_stage = [&](int s, int kc) {
#pragma unroll
        for (int i = 0; i < 8; i++) {
            int idx = tid + i * 256;         // 0..2047
            int tile = idx >> 9;             // 0..3
            int c = idx & 511;               // 0..511
            int row = c >> 2, seg = c & 3;
            const __nv_bfloat16* src = gsrc[tile] + (size_t)row * HH + kc * 32 + seg * 8;
            uint32_t dst = sb + s * STAGEB + tile * TILEB + row * LROW + seg * 16;
            CP16(dst, src);
        }
    };

    // ldmatrix lane addressing (precomputed)
    const uint32_t a_lane_off = (uint32_t)((lane & 15) * LROW + (lane >> 4) * 16);
    const uint32_t b_lane_row = (uint32_t)((lane & 7) + ((lane >> 4) << 3));
    const uint32_t b_lane_off = (uint32_t)(b_lane_row * LROW + ((lane >> 3) & 1) * 16);

    load_stage(0, 0);
    CP_COMMIT();

    const int NT = HH / 32;   // 32
    for (int kc = 0; kc < NT; kc++) {
        int s = kc & 1;
        if (kc + 1 < NT) {
            load_stage(s ^ 1, kc + 1);
            CP_COMMIT();
            CP_WAIT1();
        } else {
            CP_WAIT0();
        }
        __syncthreads();

        uint32_t Ah = sb + s * STAGEB;
        uint32_t Al = Ah + TILEB;
        uint32_t Bh = Al + TILEB;
        uint32_t Bl = Bh + TILEB;

#pragma unroll
        for (int ks = 0; ks < 2; ks++) {
            uint32_t kb = (uint32_t)(ks * 32);
            uint32_t bH[8], bL[8];
            ldm_x4(bH + 0, Bh + (warp_n * 32 +  0) * LROW + kb + b_lane_off);
            ldm_x4(bH + 4, Bh + (warp_n * 32 + 16) * LROW + kb + b_lane_off);
            ldm_x4(bL + 0, Bl + (warp_n * 32 +  0) * LROW + kb + b_lane_off);
            ldm_x4(bL + 4, Bl + (warp_n * 32 + 16) * LROW + kb + b_lane_off);
#pragma unroll
            for (int mi = 0; mi < 4; mi++) {
                uint32_t ar[4];
                uint32_t rowoff = (warp_m * 64 + mi * 16) * LROW + kb + a_lane_off;
                ldm_x4(ar, Ah + rowoff);
#pragma unroll
                for (int ni = 0; ni < 4; ni++) {
                    mma16816(acc[mi][ni], ar[0], ar[1], ar[2], ar[3],
                             bH[ni * 2], bH[ni * 2 + 1]);
                    mma16816(acc[mi][ni], ar[0], ar[1], ar[2], ar[3],
                             bL[ni * 2], bL[ni * 2 + 1]);
                }
                ldm_x4(ar, Al + rowoff);
#pragma unroll
                for (int ni = 0; ni < 4; ni++) {
                    mma16816(acc[mi][ni], ar[0], ar[1], ar[2], ar[3],
                             bH[ni * 2], bH[ni * 2 + 1]);
                }
            }
        }
        __syncthreads();
    }

    // ---- epilogue: add bias, scatter to out[b, t+1, :]
    int gp = lane >> 2;
    int tc = (lane & 3) * 2;
#pragma unroll
    for (int mi = 0; mi < 4; mi++) {
        int r0 = m0 + warp_m * 64 + mi * 16 + gp;
        int r1 = r0 + 8;
        bool v0 = r0 < MM, v1 = r1 < MM;
        float* row0 = v0 ? out + ((size_t)(r0 & 15) * LL + ((r0 >> 4) + 1)) * VV : out;
        float* row1 = v1 ? out + ((size_t)(r1 & 15) * LL + ((r1 >> 4) + 1)) * VV : out;
#pragma unroll
        for (int ni = 0; ni < 4; ni++) {
            int c = n0 + warp_n * 32 + ni * 8 + tc;
            float2 bb = *(const float2*)(fc_b + c);
            if (v0) {
                float2 v = {acc[mi][ni][0] + bb.x, acc[mi][ni][1] + bb.y};
                *(float2*)(row0 + c) = v;
            }
            if (v1) {
                float2 v = {acc[mi][ni][2] + bb.x, acc[mi][ni][3] + bb.y};
                *(float2*)(row1 + c) = v;
            }
        }
    }
}

// =====================================================================
// Launch
// =====================================================================
extern "C" void kernel_launch(void* const* d_in, const int* in_sizes, int n_in,
                              void* d_out, int out_size) {
    const float* latent = (const float*)d_in[0];
    const float* emb    = (const float*)d_in[1];
    const float* W_ih   = (const float*)d_in[2];
    const float* W_hh   = (const float*)d_in[3];
    const float* b_ih   = (const float*)d_in[4];
    const float* b_hh   = (const float*)d_in[5];
    const float* fc_w   = (const float*)d_in[6];
    const float* fc_b   = (const float*)d_in[7];
    const int*   target = (const int*)d_in[8];
    // d_in[9] = tf_mask: all True -> recurrence independent of logits
    float* out = (float*)d_out;
    (void)in_sizes; (void)n_in; (void)out_size;

    cudaFuncSetAttribute(k_logits_mma, cudaFuncAttributeMaxDynamicSharedMemorySize,
                         LOG_SMEM);

    k_zero<<<(BB * (VV / 4) + 255) / 256, 256>>>(out);
    k_lat<<<(BB * 4 * HH) / 256, 256>>>(latent, W_ih, b_ih, b_hh);
    k_split_w<<<(int)(((size_t)VV * HH / 4 + 255) / 256), 256>>>(fc_w);
    k_padH<<<((MPAD - MM) * HH + 255) / 256, 256>>>();

    {
        dim3 grid(4 * HH / TBN, (MM + TBM - 1) / TBM);   // (32, 16)
        k_z<<<grid, 256>>>(emb, W_ih, target);
    }

    for (int t = 0; t < STEPS; t++) {
        k_step<<<HH / 4, 128>>>(W_hh, t);
    }

    {
        dim3 grid(MPAD / 128, VV / 128);                 // (16, 250), M fastest
        k_logits_mma<<<grid, 256, LOG_SMEM>>>(fc_b, out);
    }
}

// round 12
// speedup vs baseline: 1.3823x; 1.0490x over previous
#include <cuda_runtime.h>
#include <cuda_bf16.h>
#include <math.h>
#include <stdint.h>

// Shapes (fixed by the problem)
#define BB   16
#define LL   128
#define VV   32000
#define EE   512
#define HH   1024
#define DD   512
#define STEPS 127
#define MM   (STEPS*BB)     // 2032, time-major m = t*16 + b
#define MPAD 2048

#define TBM 128
#define TBN 128
#define TBK 16

// packed-tile geometry for the mma logits GEMM
#define LROW 80                          // padded bytes per row (32 bf16 + 16B pad)
#define TILEB (128 * LROW)               // 10240 B : one 128x32 bf16 tile
#define BLKB  (2 * TILEB)                // 20480 B : hi tile + lo tile
#define NKC   (HH / 32)                  // 32 k-chunks
#define NTILES_N (VV / 128)              // 250
#define NTILES_M (MPAD / 128)            // 16

// -------- scratch (static device globals; no allocation) --------
__device__ float g_Z[MM * 4 * HH];
__device__ float g_H[MM * HH];
__device__ float g_C[BB * HH];
__device__ float g_Lp[BB * 4 * HH];
__device__ uint8_t g_Wp[(size_t)NTILES_N * NKC * BLKB];   // 163.84 MB packed fc_w hi/lo
__device__ uint8_t g_Ap[(size_t)NTILES_M * NKC * BLKB];   // 10.49 MB packed H hi/lo

// ============================ PTX helpers (sm_90 baseline, family-safe) ======
static __device__ __forceinline__ uint32_t s2u(const void* p) {
    uint32_t a;
    asm("{ .reg .u64 t; cvta.to.shared.u64 t, %1; cvt.u32.u64 %0, t; }"
        : "=r"(a) : "l"(p));
    return a;
}

__device__ __forceinline__ void mma16816(float* c, uint32_t a0, uint32_t a1,
                                         uint32_t a2, uint32_t a3,
                                         uint32_t b0, uint32_t b1) {
    asm volatile(
        "mma.sync.aligned.m16n8k16.row.col.f32.bf16.bf16.f32 "
        "{%0,%1,%2,%3}, {%4,%5,%6,%7}, {%8,%9}, {%0,%1,%2,%3};"
        : "+f"(c[0]), "+f"(c[1]), "+f"(c[2]), "+f"(c[3])
        : "r"(a0), "r"(a1), "r"(a2), "r"(a3), "r"(b0), "r"(b1));
}

__device__ __forceinline__ void ldm_x4(uint32_t* r, uint32_t addr) {
    asm volatile("ldmatrix.sync.aligned.m8n8.x4.shared.b16 {%0,%1,%2,%3}, [%4];"
        : "=r"(r[0]), "=r"(r[1]), "=r"(r[2]), "=r"(r[3]) : "r"(addr));
}

__device__ __forceinline__ void bulk_g2s(uint32_t dst, const void* src,
                                         uint32_t bytes, uint32_t mb) {
    asm volatile(
        "cp.async.bulk.shared::cluster.global.mbarrier::complete_tx::bytes "
        "[%0], [%1], %2, [%3];"
        :: "r"(dst), "l"(src), "r"(bytes), "r"(mb) : "memory");
}

#define MBAR_INIT(mb, cnt) \
    asm volatile("mbarrier.init.shared.b64 [%0], %1;" :: "r"(mb), "r"((uint32_t)(cnt)) : "memory")

#define MBAR_EXPECT_TX(mb, bytes) \
    asm volatile("mbarrier.arrive.expect_tx.shared.b64 _, [%0], %1;" \
                 :: "r"(mb), "r"((uint32_t)(bytes)) : "memory")

#define MBAR_WAIT(mbar_smem_addr, phase_parity) do {                                     \
    uint32_t _mbar = (uint32_t)(mbar_smem_addr);                                         \
    uint32_t _parity = (uint32_t)(phase_parity);                                         \
    uint32_t _done;                                                                      \
    asm volatile(                                                                        \
        "{\n\t"                                                                          \
        ".reg .pred p;\n\t"                                                              \
        "mbarrier.try_wait.parity.acquire.cta.shared::cta.b64 p, [%1], %2;\n\t"          \
        "selp.b32 %0, 1, 0, p;\n\t"                                                      \
        "}"                                                                              \
        : "=r"(_done) : "r"(_mbar), "r"(_parity) : "memory");                            \
    if (!_done) {                                                                        \
        asm volatile(                                                                    \
            "{\n\t"                                                                      \
            ".reg .pred P1;\n\t"                                                         \
            "WAIT_LOOP_%=:\n\t"                                                          \
            "mbarrier.try_wait.parity.acquire.cta.shared::cta.b64 P1, [%0], %1, 0x989680;\n\t" \
            "@P1 bra.uni WAIT_DONE_%=;\n\t"                                              \
            "bra.uni WAIT_LOOP_%=;\n\t"                                                  \
            "WAIT_DONE_%=:\n\t"                                                          \
            "}"                                                                          \
            :: "r"(_mbar), "r"(_parity) : "memory");                                     \
    }                                                                                    \
} while (0)

// pack 8 consecutive floats into 16B of bf16 hi and 16B of bf16 lo
__device__ __forceinline__ void split8(const float* src, uint4* hi, uint4* lo) {
    uint32_t h[4], l[4];
#pragma unroll
    for (int p = 0; p < 4; p++) {
        float x0 = src[p * 2], x1 = src[p * 2 + 1];
        __nv_bfloat16 h0 = __float2bfloat16(x0);
        __nv_bfloat16 h1 = __float2bfloat16(x1);
        __nv_bfloat16 l0 = __float2bfloat16(x0 - __bfloat162float(h0));
        __nv_bfloat16 l1 = __float2bfloat16(x1 - __bfloat162float(h1));
        h[p] = ((uint32_t)__bfloat16_as_ushort(h1) << 16) | __bfloat16_as_ushort(h0);
        l[p] = ((uint32_t)__bfloat16_as_ushort(l1) << 16) | __bfloat16_as_ushort(l0);
    }
    *hi = make_uint4(h[0], h[1], h[2], h[3]);
    *lo = make_uint4(l[0], l[1], l[2], l[3]);
}

// =====================================================================
// zero out[:, 0, :]
// =====================================================================
__global__ void k_zero(float* __restrict__ out) {
    int i = blockIdx.x * 256 + threadIdx.x;
    if (i < BB * (VV / 4)) {
        int b  = i / (VV / 4);
        int v4 = i % (VV / 4);
        float4 z = {0.f, 0.f, 0.f, 0.f};
        ((float4*)(out + (size_t)b * LL * VV))[v4] = z;
    }
}

// =====================================================================
// Lp[b][j] = b_ih[j] + b_hh[j] + latent[b] . W_ih[j, 512:1024]
// =====================================================================
__global__ void __launch_bounds__(256) k_lat(
    const float* __restrict__ latent, const float* __restrict__ W_ih,
    const float* __restrict__ b_ih,   const float* __restrict__ b_hh) {
    int g = blockIdx.x * 256 + threadIdx.x;
    int j = g >> 4;
    int b = g & 15;
    const float4* wl = (const float4*)(W_ih + (size_t)j * (EE + DD) + EE);
    const float4* lv = (const float4*)(latent + b * DD);
    float acc = 0.f;
#pragma unroll 8
    for (int k = 0; k < DD / 4; k++) {
        float4 w = wl[k], x = lv[k];
        acc += w.x * x.x + w.y * x.y + w.z * x.z + w.w * x.w;
    }
    g_Lp[b * 4 * HH + j] = acc + b_ih[j] + b_hh[j];
}

// =====================================================================
// split + repack fc_w -> g_Wp[ntile][kc][128x80 hi][128x80 lo]
// thread i: n = i/128, c8 = i%128 (8-float chunk of the n-th row)
// =====================================================================
__global__ void __launch_bounds__(256) k_split_w(const float* __restrict__ fc_w) {
    int i = blockIdx.x * 256 + threadIdx.x;
    if (i >= VV * 128) return;
    int n = i >> 7, c8 = i & 127;
    int k = c8 * 8;
    int T = n >> 7, rl = n & 127;
    int kc = k >> 5, ks = k & 31;
    uint4 hi, lo;
    split8(fc_w + (size_t)n * HH + k, &hi, &lo);
    size_t base = ((size_t)T * NKC + kc) * BLKB + (size_t)rl * LROW + ks * 2;
    *(uint4*)(g_Wp + base)         = hi;
    *(uint4*)(g_Wp + base + TILEB) = lo;
}

// =====================================================================
// split + repack H -> g_Ap (rows >= MM zero-padded)
// =====================================================================
__global__ void __launch_bounds__(256) k_packA() {
    int i = blockIdx.x * 256 + threadIdx.x;
    if (i >= MPAD * 128) return;
    int m = i >> 7, c8 = i & 127;
    int k = c8 * 8;
    int T = m >> 7, rl = m & 127;
    int kc = k >> 5, ks = k & 31;
    uint4 hi, lo;
    if (m < MM) {
        split8(g_H + (size_t)m * HH + k, &hi, &lo);
    } else {
        hi = make_uint4(0, 0, 0, 0);
        lo = make_uint4(0, 0, 0, 0);
    }
    size_t base = ((size_t)T * NKC + kc) * BLKB + (size_t)rl * LROW + ks * 2;
    *(uint4*)(g_Ap + base)         = hi;
    *(uint4*)(g_Ap + base + TILEB) = lo;
}

// =====================================================================
// Z = gather(emb, tok) @ W_ih[:, :512]^T + Lp   (fp32 SGEMM)
// =====================================================================
__global__ void __launch_bounds__(256) k_z(
    const float* __restrict__ emb, const float* __restrict__ W_ih,
    const int* __restrict__ target) {
    const int M = MM, K = EE, ldb = EE + DD;
    __shared__ float As[2][TBK][TBM + 4];
    __shared__ float Bs[2][TBK][TBN + 4];
    int tid = threadIdx.x;
    int m0 = blockIdx.y * TBM;
    int n0 = blockIdx.x * TBN;

    int lr = tid >> 2;
    int lk = (tid & 3) * 4;

    int r1 = m0 + lr, r2 = m0 + lr + 64;
    bool v1 = (r1 < M), v2 = (r2 < M);
    const float* arow1 = emb + (size_t)(v1 ? target[(r1 & 15) * LL + (r1 >> 4)] : 0) * EE;
    const float* arow2 = emb + (size_t)(v2 ? target[(r2 & 15) * LL + (r2 >> 4)] : 0) * EE;
    const float* brow1 = W_ih + (size_t)(n0 + lr) * ldb;
    const float* brow2 = W_ih + (size_t)(n0 + lr + 64) * ldb;

    float acc[8][8];
#pragma unroll
    for (int i = 0; i < 8; i++)
#pragma unroll
        for (int j = 0; j < 8; j++) acc[i][j] = 0.f;

    int tx = tid & 15, ty = tid >> 4;
    const float4 zero4 = {0.f, 0.f, 0.f, 0.f};

    float4 pa0, pa1, pb0, pb1;
    {
        int gk = lk;
        pa0 = v1 ? *(const float4*)(arow1 + gk) : zero4;
        pa1 = v2 ? *(const float4*)(arow2 + gk) : zero4;
        pb0 = *(const float4*)(brow1 + gk);
        pb1 = *(const float4*)(brow2 + gk);
        As[0][lk + 0][lr] = pa0.x; As[0][lk + 1][lr] = pa0.y; As[0][lk + 2][lr] = pa0.z; As[0][lk + 3][lr] = pa0.w;
        As[0][lk + 0][lr + 64] = pa1.x; As[0][lk + 1][lr + 64] = pa1.y; As[0][lk + 2][lr + 64] = pa1.z; As[0][lk + 3][lr + 64] = pa1.w;
        Bs[0][lk + 0][lr] = pb0.x; Bs[0][lk + 1][lr] = pb0.y; Bs[0][lk + 2][lr] = pb0.z; Bs[0][lk + 3][lr] = pb0.w;
        Bs[0][lk + 0][lr + 64] = pb1.x; Bs[0][lk + 1][lr + 64] = pb1.y; Bs[0][lk + 2][lr + 64] = pb1.z; Bs[0][lk + 3][lr + 64] = pb1.w;
    }
    __syncthreads();

    const int NT = K / TBK;
    int cur = 0;
    for (int kt = 0; kt < NT; kt++) {
        if (kt + 1 < NT) {
            int gk = (kt + 1) * TBK + lk;
            pa0 = v1 ? *(const float4*)(arow1 + gk) : zero4;
            pa1 = v2 ? *(const float4*)(arow2 + gk) : zero4;
            pb0 = *(const float4*)(brow1 + gk);
            pb1 = *(const float4*)(brow2 + gk);
        }
#pragma unroll
        for (int k = 0; k < TBK; k++) {
            float4 a0 = *(const float4*)&As[cur][k][ty * 4];
            float4 a1 = *(const float4*)&As[cur][k][ty * 4 + 64];
            float4 b0 = *(const float4*)&Bs[cur][k][tx * 4];
            float4 b1 = *(const float4*)&Bs[cur][k][tx * 4 + 64];
            float a[8] = {a0.x, a0.y, a0.z, a0.w, a1.x, a1.y, a1.z, a1.w};
            float b[8] = {b0.x, b0.y, b0.z, b0.w, b1.x, b1.y, b1.z, b1.w};
#pragma unroll
            for (int i = 0; i < 8; i++)
#pragma unroll
                for (int j = 0; j < 8; j++) acc[i][j] += a[i] * b[j];
        }
        if (kt + 1 < NT) {
            int nx = cur ^ 1;
            As[nx][lk + 0][lr] = pa0.x; As[nx][lk + 1][lr] = pa0.y; As[nx][lk + 2][lr] = pa0.z; As[nx][lk + 3][lr] = pa0.w;
            As[nx][lk + 0][lr + 64] = pa1.x; As[nx][lk + 1][lr + 64] = pa1.y; As[nx][lk + 2][lr + 64] = pa1.z; As[nx][lk + 3][lr + 64] = pa1.w;
            Bs[nx][lk + 0][lr] = pb0.x; Bs[nx][lk + 1][lr] = pb0.y; Bs[nx][lk + 2][lr] = pb0.z; Bs[nx][lk + 3][lr] = pb0.w;
            Bs[nx][lk + 0][lr + 64] = pb1.x; Bs[nx][lk + 1][lr + 64] = pb1.y; Bs[nx][lk + 2][lr + 64] = pb1.z; Bs[nx][lk + 3][lr + 64] = pb1.w;
            __syncthreads();
            cur = nx;
        }
    }

#pragma unroll
    for (int i = 0; i < 8; i++) {
        int m = m0 + ty * 4 + (i & 3) + ((i >= 4) ? 64 : 0);
        if (m < M) {
            int b = m & 15;
            const float4 l0 = *(const float4*)(g_Lp + b * 4 * HH + n0 + tx * 4);
            const float4 l1 = *(const float4*)(g_Lp + b * 4 * HH + n0 + tx * 4 + 64);
            float4 v0 = {acc[i][0] + l0.x, acc[i][1] + l0.y, acc[i][2] + l0.z, acc[i][3] + l0.w};
            float4 w0 = {acc[i][4] + l1.x, acc[i][5] + l1.y, acc[i][6] + l1.z, acc[i][7] + l1.w};
            float* zrow = g_Z + (size_t)m * 4 * HH + n0 + tx * 4;
            *(float4*)zrow = v0;
            *(float4*)(zrow + 64) = w0;
        }
    }
}

// =====================================================================
// One LSTM step (fp32, compute-bound at ~3.7us/step floor)
// =====================================================================
__device__ __forceinline__ float sigf(float x) { return 1.0f / (1.0f + expf(-x)); }

__global__ void __launch_bounds__(128) k_step(const float* __restrict__ Whh, int t) {
    int warp = threadIdx.x >> 5;
    int lane = threadIdx.x & 31;
    int b  = lane >> 1;
    int gp = lane & 1;
    int jh = blockIdx.x * 4 + warp;

    float a0 = 0.f, a1 = 0.f, a2 = 0.f, a3 = 0.f;
    if (t > 0) {
        const float4* w0 = (const float4*)(Whh + ((size_t)(2 * gp)     * HH + jh) * HH);
        const float4* w1 = (const float4*)(Whh + ((size_t)(2 * gp + 1) * HH + jh) * HH);
        const float4* hv = (const float4*)(g_H + ((size_t)(t - 1) * BB + b) * HH);
#pragma unroll 4
        for (int k = 0; k < HH / 4; k += 2) {
            float4 x  = w0[k],     y  = w1[k],     h  = hv[k];
            a0 += x.x * h.x + x.y * h.y + x.z * h.z + x.w * h.w;
            a1 += y.x * h.x + y.y * h.y + y.z * h.z + y.w * h.w;
            float4 x2 = w0[k + 1], y2 = w1[k + 1], h2 = hv[k + 1];
            a2 += x2.x * h2.x + x2.y * h2.y + x2.z * h2.z + x2.w * h2.w;
            a3 += y2.x * h2.x + y2.y * h2.y + y2.z * h2.z + y2.w * h2.w;
        }
    }
    const float* Zr = g_Z + ((size_t)t * BB + b) * 4 * HH;
    float p0 = a0 + a2 + Zr[(2 * gp)     * HH + jh];
    float p1 = a1 + a3 + Zr[(2 * gp + 1) * HH + jh];
    float q0 = __shfl_xor_sync(0xffffffffu, p0, 1);
    float q1 = __shfl_xor_sync(0xffffffffu, p1, 1);
    float gi, gf, gg, go;
    if (gp == 0) { gi = p0; gf = p1; gg = q0; go = q1; }
    else         { gi = q0; gf = q1; gg = p0; go = p1; }
    float cprev = (t == 0) ? 0.f : g_C[b * HH + jh];
    float cn = sigf(gf) * cprev + sigf(gi) * tanhf(gg);
    float hn = sigf(go) * tanhf(cn);
    if (gp == 0) {
        g_C[b * HH + jh] = cn;
        g_H[((size_t)t * BB + b) * HH + jh] = hn;
    }
}

// =====================================================================
// logits via mma.sync bf16 3-product split, staged by cp.async.bulk:
//   D = Ahi*Bhi + Ahi*Blo + Alo*Bhi  (fp32 accum)
// CTA tile 128x128, BK=32; per stage ONE 20480B bulk for A(hi+lo) and
// ONE for B(hi+lo) from the pre-packed, pre-padded global tiles.
// mbarrier-paced double buffer. grid (16 M fastest, 250 N) for L2 reuse.
// =====================================================================
#define STAGEB (2 * BLKB)                // 40960 B  [Ahi][Alo][Bhi][Blo]
#define LOG_SMEM (2 * STAGEB + 32)       // + mbarriers

__global__ void __launch_bounds__(256) k_logits_mma(
    const float* __restrict__ fc_b, float* __restrict__ out) {
    extern __shared__ char smem[];
    const uint32_t sb = s2u(smem);
    const uint32_t mb[2] = {sb + 2 * STAGEB, sb + 2 * STAGEB + 8};

    const int tid = threadIdx.x;
    const int wid = tid >> 5, lane = tid & 31;
    const int warp_m = wid >> 2;        // 0..1
    const int warp_n = wid & 3;         // 0..3
    const int mT = blockIdx.x;          // 0..15
    const int nT = blockIdx.y;          // 0..249
    const int m0 = mT * 128;
    const int n0 = nT * 128;

    const uint8_t* Asrc = g_Ap + (size_t)mT * NKC * BLKB;
    const uint8_t* Bsrc = g_Wp + (size_t)nT * NKC * BLKB;

    if (tid == 0) { MBAR_INIT(mb[0], 1); MBAR_INIT(mb[1], 1); }
    __syncthreads();

    if (tid == 0) {
#pragma unroll
        for (int s = 0; s < 2; s++) {
            MBAR_EXPECT_TX(mb[s], STAGEB);
            bulk_g2s(sb + s * STAGEB,        Asrc + (size_t)s * BLKB, BLKB, mb[s]);
            bulk_g2s(sb + s * STAGEB + BLKB, Bsrc + (size_t)s * BLKB, BLKB, mb[s]);
        }
    }

    float acc[4][4][4];
#pragma unroll
    for (int i = 0; i < 4; i++)
#pragma unroll
        for (int j = 0; j < 4; j++)
#pragma unroll
            for (int q = 0; q < 4; q++) acc[i][j][q] = 0.f;

    // ldmatrix lane addressing
    const uint32_t a_lane_off = (uint32_t)((lane & 15) * LROW + (lane >> 4) * 16);
    const uint32_t b_lane_row = (uint32_t)((lane & 7) + ((lane >> 4) << 3));
    const uint32_t b_lane_off = (uint32_t)(b_lane_row * LROW + ((lane >> 3) & 1) * 16);

    int ph0 = 0, ph1 = 0;
    for (int kc = 0; kc < NKC; kc++) {
        int s = kc & 1;
        if (s == 0) { MBAR_WAIT(mb[0], ph0); ph0 ^= 1; }
        else        { MBAR_WAIT(mb[1], ph1); ph1 ^= 1; }

        uint32_t Ah = sb + s * STAGEB;
        uint32_t Al = Ah + TILEB;
        uint32_t Bh = Al + TILEB;
        uint32_t Bl = Bh + TILEB;

#pragma unroll
        for (int ks = 0; ks < 2; ks++) {
            uint32_t kb = (uint32_t)(ks * 32);
            uint32_t bH[8], bL[8];
            ldm_x4(bH + 0, Bh + (warp_n * 32 +  0) * LROW + kb + b_lane_off);
            ldm_x4(bH + 4, Bh + (warp_n * 32 + 16) * LROW + kb + b_lane_off);
            ldm_x4(bL + 0, Bl + (warp_n * 32 +  0) * LROW + kb + b_lane_off);
            ldm_x4(bL + 4, Bl + (warp_n * 32 + 16) * LROW + kb + b_lane_off);
#pragma unroll
            for (int mi = 0; mi < 4; mi++) {
                uint32_t ar[4];
                uint32_t rowoff = (warp_m * 64 + mi * 16) * LROW + kb + a_lane_off;
                ldm_x4(ar, Ah + rowoff);
#pragma unroll
                for (int ni = 0; ni < 4; ni++) {
                    mma16816(acc[mi][ni], ar[0], ar[1], ar[2], ar[3],
                             bH[ni * 2], bH[ni * 2 + 1]);
                    mma16816(acc[mi][ni], ar[0], ar[1], ar[2], ar[3],
                             bL[ni * 2], bL[ni * 2 + 1]);
                }
                ldm_x4(ar, Al + rowoff);
#pragma unroll
                for (int ni = 0; ni < 4; ni++) {
                    mma16816(acc[mi][ni], ar[0], ar[1], ar[2], ar[3],
                             bH[ni * 2], bH[ni * 2 + 1]);
                }
            }
        }
        __syncthreads();   // all warps done reading stage s
        if (kc + 2 < NKC && tid == 0) {
            MBAR_EXPECT_TX(mb[s], STAGEB);
            bulk_g2s(sb + s * STAGEB,        Asrc + (size_t)(kc + 2) * BLKB, BLKB, mb[s]);
            bulk_g2s(sb + s * STAGEB + BLKB, Bsrc + (size_t)(kc + 2) * BLKB, BLKB, mb[s]);
        }
    }

    // ---- epilogue: add bias, scatter to out[b, t+1, :]
    int gp = lane >> 2;
    int tc = (lane & 3) * 2;
#pragma unroll
    for (int mi = 0; mi < 4; mi++) {
        int r0 = m0 + warp_m * 64 + mi * 16 + gp;
        int r1 = r0 + 8;
        bool v0 = r0 < MM, v1 = r1 < MM;
        float* row0 = v0 ? out + ((size_t)(r0 & 15) * LL + ((r0 >> 4) + 1)) * VV : out;
        float* row1 = v1 ? out + ((size_t)(r1 & 15) * LL + ((r1 >> 4) + 1)) * VV : out;
#pragma unroll
        for (int ni = 0; ni < 4; ni++) {
            int c = n0 + warp_n * 32 + ni * 8 + tc;
            float2 bb = *(const float2*)(fc_b + c);
            if (v0) {
                float2 v = {acc[mi][ni][0] + bb.x, acc[mi][ni][1] + bb.y};
                *(float2*)(row0 + c) = v;
            }
            if (v1) {
                float2 v = {acc[mi][ni][2] + bb.x, acc[mi][ni][3] + bb.y};
                *(float2*)(row1 + c) = v;
            }
        }
    }
}

// =====================================================================
// Launch
// =====================================================================
extern "C" void kernel_launch(void* const* d_in, const int* in_sizes, int n_in,
                              void* d_out, int out_size) {
    const float* latent = (const float*)d_in[0];
    const float* emb    = (const float*)d_in[1];
    const float* W_ih   = (const float*)d_in[2];
    const float* W_hh   = (const float*)d_in[3];
    const float* b_ih   = (const float*)d_in[4];
    const float* b_hh   = (const float*)d_in[5];
    const float* fc_w   = (const float*)d_in[6];
    const float* fc_b   = (const float*)d_in[7];
    const int*   target = (const int*)d_in[8];
    // d_in[9] = tf_mask: all True -> recurrence independent of logits
    float* out = (float*)d_out;
    (void)in_sizes; (void)n_in; (void)out_size;

    cudaFuncSetAttribute(k_logits_mma, cudaFuncAttributeMaxDynamicSharedMemorySize,
                         LOG_SMEM);

    k_zero<<<(BB * (VV / 4) + 255) / 256, 256>>>(out);
    k_lat<<<(BB * 4 * HH) / 256, 256>>>(latent, W_ih, b_ih, b_hh);
    k_split_w<<<(VV * 128) / 256, 256>>>(fc_w);

    {
        dim3 grid(4 * HH / TBN, (MM + TBM - 1) / TBM);   // (32, 16)
        k_z<<<grid, 256>>>(emb, W_ih, target);
    }

    for (int t = 0; t < STEPS; t++) {
        k_step<<<HH / 4, 128>>>(W_hh, t);
    }

    k_packA<<<(MPAD * 128) / 256, 256>>>();

    {
        dim3 grid(NTILES_M, NTILES_N);                   // (16, 250), M fastest
        k_logits_mma<<<grid, 256, LOG_SMEM>>>(fc_b, out);
    }
}